// round 3
// baseline (speedup 1.0000x reference)
#include <cuda_runtime.h>

// Problem constants
#define NB    256      // batch
#define NH    3        // heads
#define CC    64       // channels (c == o)
#define NN    23       // nodes
#define LL    35       // seq len
#define FEAT  529      // 23*23
#define LC    5        // l-chunk size
#define NCHUNK 7       // 35 / 5
#define KINV  (1.0f/2240.0f)   // 1/(o*l)

// ---------------- device scratch (no allocations allowed) ----------------
__device__ float g_G[NH*64*65];        // G[h][c2][c1], rows padded to 65
__device__ float g_v1[NH*CC];          // v1[h][c] = sum_o cb2[h,o]*cw1[h,o,c]
__device__ float g_v2[NH*CC];          // v2[h][c] = sum_o cb1[h,o]*cw2[h,o,c]
__device__ float g_sc[NH];             // sum_o cb1*cb2
__device__ float g_attm[NB*NH*FEAT];   // pre-BN attention
__device__ float g_scale[NH*FEAT];     // gamma/sqrt(var+eps)
__device__ float g_shift[NH*FEAT];     // beta - mean*scale
__device__ float g_A[NB*NH*FEAT];      // final adjacency
__device__ float g_gcn[NB*CC*NN*LL];   // gcn output before seq matmul

// ---------------- k0: precompute G, v1, v2, s ----------------
__global__ void k0_pre(const float* __restrict__ cw1, const float* __restrict__ cb1,
                       const float* __restrict__ cw2, const float* __restrict__ cb2) {
    __shared__ float s1[64*64];
    __shared__ float s2[64*64];
    int h = blockIdx.x, t = threadIdx.x;
    for (int i = t; i < 4096; i += 256) { s1[i] = cw1[h*4096+i]; s2[i] = cw2[h*4096+i]; }
    __syncthreads();
    for (int e = t; e < 4096; e += 256) {
        int c2 = e >> 6, c1 = e & 63;
        float acc = 0.f;
        #pragma unroll 8
        for (int o = 0; o < 64; o++) acc += s2[o*64+c2] * s1[o*64+c1];
        g_G[h*64*65 + c2*65 + c1] = acc;
    }
    if (t < 64) {
        float a1 = 0.f, a2 = 0.f;
        for (int o = 0; o < 64; o++) {
            a1 += cb2[h*64+o] * s1[o*64+t];
            a2 += cb1[h*64+o] * s2[o*64+t];
        }
        g_v1[h*64+t] = a1;
        g_v2[h*64+t] = a2;
    }
    if (t == 64) {
        float a = 0.f;
        for (int o = 0; o < 64; o++) a += cb1[h*64+o]*cb2[h*64+o];
        g_sc[h] = a;
    }
}

// ---------------- k1: attention matrices (pre-BN) ----------------
// per-block (one batch b): Q[h,m,n] = sum_l X_l^T G_h X_l, plus bias terms.
// smem: sG[3*64*65] | sxt[64*115] | sW[192*23] | sXs[64*23] | st1[69] | st2[69]
#define SM1_FLOATS (NH*64*65 + 64*115 + 192*23 + 64*23 + 69 + 69)

__global__ __launch_bounds__(256, 2) void k1_attm(const float* __restrict__ x) {
    extern __shared__ float sm[];
    float* sG  = sm;                    // 12480
    float* sxt = sG  + NH*64*65;        // 7360  : [c][n*5+li]
    float* sW  = sxt + 64*115;          // 4416  : [(h*64+c2)*23+n]
    float* sXs = sW  + 192*23;          // 1472  : [c*23+n]
    float* st1 = sXs + 64*23;           // 69
    float* st2 = st1 + 69;              // 69

    int b = blockIdx.x, t = threadIdx.x;

    for (int i = t; i < NH*64*65; i += 256) sG[i] = g_G[i];
    for (int i = t; i < 1472; i += 256) sXs[i] = 0.f;

    // W-phase mapping: 64 row-tiles (3 rows) x 4 col-tiles (6 cols)
    int rt = t & 63, ct = t >> 6;
    int r0 = rt * 3;
    int n0 = ct * 6;

    // Q-phase mapping: 192 active threads; tile 3m x 3n per head
    int qh = t / 64, qs = t % 64;
    int qmt = qs & 7, qnt = qs >> 3;
    bool qact = (t < 192);
    int m0 = qmt * 3, nq0 = qnt * 3;

    float q[3][3];
    #pragma unroll
    for (int i = 0; i < 3; i++)
        #pragma unroll
        for (int j = 0; j < 3; j++) q[i][j] = 0.f;

    __syncthreads();

    for (int ch = 0; ch < NCHUNK; ch++) {
        int l0 = ch * LC;
        for (int idx = t; idx < 7360; idx += 256) {
            int c = idx / 115, r = idx % 115;
            int n = r / 5, li = r % 5;
            sxt[idx] = x[((b*64 + c)*23 + n)*35 + l0 + li];
        }
        __syncthreads();

        // Xs accumulation (each entry owned by one thread, read only at the end)
        for (int e = t; e < 1472; e += 256) {
            float a = sXs[e];
            #pragma unroll
            for (int li = 0; li < 5; li++) a += sxt[e*5 + li];
            sXs[e] = a;
        }

        for (int li = 0; li < LC; li++) {
            // ---- W phase: W[h,c2,n] = sum_c1 G[h,c2,c1] * x[c1,n,li]
            float wacc[3][6];
            #pragma unroll
            for (int i = 0; i < 3; i++)
                #pragma unroll
                for (int j = 0; j < 6; j++) wacc[i][j] = 0.f;
            #pragma unroll 4
            for (int c1 = 0; c1 < 64; c1++) {
                float xv[6];
                #pragma unroll
                for (int j = 0; j < 6; j++) {
                    int nj = n0 + j; if (nj > 22) nj = 22;
                    xv[j] = sxt[c1*115 + nj*5 + li];
                }
                float gv[3];
                #pragma unroll
                for (int i = 0; i < 3; i++) gv[i] = sG[(r0 + i)*65 + c1];
                #pragma unroll
                for (int i = 0; i < 3; i++)
                    #pragma unroll
                    for (int j = 0; j < 6; j++) wacc[i][j] += gv[i] * xv[j];
            }
            #pragma unroll
            for (int i = 0; i < 3; i++)
                #pragma unroll
                for (int j = 0; j < 6; j++)
                    if (n0 + j < 23) sW[(r0 + i)*23 + n0 + j] = wacc[i][j];
            __syncthreads();

            // ---- Q phase: Q[h,m,n] += sum_c2 x[c2,m,li] * W[h,c2,n]
            if (qact) {
                #pragma unroll 4
                for (int c2 = 0; c2 < 64; c2++) {
                    float xm[3], wn[3];
                    #pragma unroll
                    for (int i = 0; i < 3; i++) {
                        int mi = m0 + i; if (mi > 22) mi = 22;
                        xm[i] = sxt[c2*115 + mi*5 + li];
                    }
                    #pragma unroll
                    for (int j = 0; j < 3; j++) {
                        int nj = nq0 + j; if (nj > 22) nj = 22;
                        wn[j] = sW[(qh*64 + c2)*23 + nj];
                    }
                    #pragma unroll
                    for (int i = 0; i < 3; i++)
                        #pragma unroll
                        for (int j = 0; j < 3; j++) q[i][j] += xm[i] * wn[j];
                }
            }
            __syncthreads();
        }
    }

    // bias-correction vectors
    if (t < 69) {
        int h = t / 23, n = t % 23;
        float a = 0.f;
        #pragma unroll 8
        for (int c = 0; c < 64; c++) a += g_v1[h*64 + c] * sXs[c*23 + n];
        st1[t] = a;
    } else if (t < 138) {
        int tt = t - 69;
        int h = tt / 23, m = tt % 23;
        float a = 0.f;
        #pragma unroll 8
        for (int c = 0; c < 64; c++) a += g_v2[h*64 + c] * sXs[c*23 + m];
        st2[tt] = a;
    }
    __syncthreads();

    if (qact) {
        float base = 35.0f * g_sc[qh];
        #pragma unroll
        for (int i = 0; i < 3; i++) {
            int m = m0 + i; if (m >= 23) continue;
            #pragma unroll
            for (int j = 0; j < 3; j++) {
                int n = nq0 + j; if (n >= 23) continue;
                float val = (q[i][j] + st2[qh*23 + m] + st1[qh*23 + n] + base) * KINV;
                g_attm[(b*NH + qh)*FEAT + m*23 + n] = val;
            }
        }
    }
}

// ---------------- k2: BN batch stats -> fused scale/shift ----------------
__global__ void k2_bn(const float* __restrict__ gamma, const float* __restrict__ beta) {
    __shared__ float ss[256];
    __shared__ float sq[256];
    int f = blockIdx.x;          // 0 .. 1586 = h*529 + feat
    int t = threadIdx.x;
    float v = g_attm[t*(NH*FEAT) + f];
    ss[t] = v; sq[t] = v*v;
    __syncthreads();
    for (int s = 128; s > 0; s >>= 1) {
        if (t < s) { ss[t] += ss[t+s]; sq[t] += sq[t+s]; }
        __syncthreads();
    }
    if (t == 0) {
        float mean = ss[0] * (1.0f/256.0f);
        float var  = sq[0] * (1.0f/256.0f) - mean*mean;
        float sc = gamma[f] * rsqrtf(var + 1e-5f);
        g_scale[f] = sc;
        g_shift[f] = beta[f] - mean * sc;
    }
}

// ---------------- k3: BN apply + softmax(axis=-2) + A assembly ----------------
__global__ void k3_soft(const float* __restrict__ att, const float* __restrict__ A_ske) {
    __shared__ float sy[FEAT];
    int bh = blockIdx.x;         // b*3 + h
    int h = bh % 3;
    int t = threadIdx.x;
    for (int e = t; e < FEAT; e += 256)
        sy[e] = g_attm[bh*FEAT + e] * g_scale[h*FEAT + e] + g_shift[h*FEAT + e];
    __syncthreads();
    if (t < 23) {   // softmax over rows m, column t
        float mx = -1e30f;
        for (int m = 0; m < 23; m++) mx = fmaxf(mx, sy[m*23 + t]);
        float s = 0.f;
        for (int m = 0; m < 23; m++) {
            float e = expf(sy[m*23 + t] - mx);
            sy[m*23 + t] = e; s += e;
        }
        float inv = 1.0f / s;
        for (int m = 0; m < 23; m++) sy[m*23 + t] *= inv;
    }
    __syncthreads();
    for (int e = t; e < FEAT; e += 256)
        g_A[bh*FEAT + e] = A_ske[h*FEAT + e] + att[h*FEAT + e] + sy[e];
}

// ---------------- k4: graph convolution -> g_gcn ----------------
// block = (b, l-chunk). MX[h] = mw[h] @ X_chunk, gcn += A[h]^T-contract(MX)
// smem: sA[3*529] | sxt[64*115] | sMX[64*115] | smw[64*65]
#define SM4_FLOATS (NH*FEAT + 64*115 + 64*115 + 64*65)

__global__ __launch_bounds__(256, 2) void k4_gcn(const float* __restrict__ x,
                                                 const float* __restrict__ mw,
                                                 const float* __restrict__ mb) {
    extern __shared__ float sm[];
    float* sA  = sm;                  // 1587
    float* sxt = sA  + NH*FEAT;       // 7360 : [c][n*5+li]
    float* sMX = sxt + 64*115;        // 7360 : [o][n*5+li]
    float* smw = sMX + 64*115;        // 4160 : [o*65+c]

    int blk = blockIdx.x;
    int b = blk / NCHUNK, ch = blk % NCHUNK;
    int l0 = ch * LC;
    int t = threadIdx.x;

    for (int i = t; i < NH*FEAT; i += 256) sA[i] = g_A[b*NH*FEAT + i];
    for (int idx = t; idx < 7360; idx += 256) {
        int c = idx / 115, r = idx % 115;
        int n = r / 5, li = r % 5;
        sxt[idx] = x[((b*64 + c)*23 + n)*35 + l0 + li];
    }

    // MX mapping: 16 o-tiles (stride-16 interleave, 4 rows) x 15 col-tiles (8 cols)
    int ot = t & 15, qt = t >> 4;
    bool mact = (qt < 15);
    int col0 = qt * 8;

    // gcn accumulator mapping: o = t%64, m-tile = t/64 (6 m) x 5 li
    int go = t & 63, gmt = t >> 6;
    int gm0 = gmt * 6;
    float gacc[6][5];
    #pragma unroll
    for (int j = 0; j < 6; j++)
        #pragma unroll
        for (int li = 0; li < 5; li++) gacc[j][li] = 0.f;

    __syncthreads();

    for (int h = 0; h < NH; h++) {
        for (int i = t; i < 4096; i += 256) {
            int o = i >> 6, c = i & 63;
            smw[o*65 + c] = mw[(h*64 + o)*64 + c];
        }
        __syncthreads();

        // MX = mw[h] @ X  (outputs 64 x 115)
        if (mact) {
            float acc[4][8];
            #pragma unroll
            for (int i = 0; i < 4; i++)
                #pragma unroll
                for (int j = 0; j < 8; j++) acc[i][j] = 0.f;
            #pragma unroll 4
            for (int c = 0; c < 64; c++) {
                float wv[4], xv[8];
                #pragma unroll
                for (int i = 0; i < 4; i++) wv[i] = smw[(ot + i*16)*65 + c];
                #pragma unroll
                for (int j = 0; j < 8; j++) {
                    int col = col0 + j;
                    xv[j] = (col < 115) ? sxt[c*115 + col] : 0.f;
                }
                #pragma unroll
                for (int i = 0; i < 4; i++)
                    #pragma unroll
                    for (int j = 0; j < 8; j++) acc[i][j] += wv[i] * xv[j];
            }
            #pragma unroll
            for (int i = 0; i < 4; i++)
                #pragma unroll
                for (int j = 0; j < 8; j++) {
                    int col = col0 + j;
                    if (col < 115) sMX[(ot + i*16)*115 + col] = acc[i][j];
                }
        }
        __syncthreads();

        // gcn[o,m,li] += sum_n MX[o,n,li] * A[h,n,m]
        #pragma unroll 1
        for (int n = 0; n < 23; n++) {
            float mx[5], av[6];
            #pragma unroll
            for (int li = 0; li < 5; li++) mx[li] = sMX[go*115 + n*5 + li];
            #pragma unroll
            for (int j = 0; j < 6; j++) {
                int m = gm0 + j; if (m > 22) m = 22;
                av[j] = sA[h*FEAT + n*23 + m];
            }
            #pragma unroll
            for (int j = 0; j < 6; j++)
                #pragma unroll
                for (int li = 0; li < 5; li++) gacc[j][li] += av[j] * mx[li];
        }
        __syncthreads();
    }

    float mbs = mb[go] + mb[64 + go] + mb[128 + go];
    #pragma unroll
    for (int j = 0; j < 6; j++) {
        int m = gm0 + j; if (m >= 23) continue;
        #pragma unroll
        for (int li = 0; li < 5; li++)
            g_gcn[((b*64 + go)*23 + m)*35 + l0 + li] = gacc[j][li] + mbs;
    }
}

// ---------------- k5: out = gcn @ weight_seq + bias ----------------
__global__ void k5_out(const float* __restrict__ ws, const float* __restrict__ bias,
                       float* __restrict__ out) {
    __shared__ float sws[LL*LL];
    __shared__ float sb[LL];
    __shared__ float srow[280];
    int t = threadIdx.x;
    for (int i = t; i < LL*LL; i += 280) sws[i] = ws[i];
    if (t < LL) sb[t] = bias[t];
    int base = blockIdx.x * 280;
    srow[t] = g_gcn[base + t];
    __syncthreads();
    int r = t / 35, j = t % 35;
    float acc = sb[j];
    #pragma unroll
    for (int l = 0; l < 35; l++) acc += srow[r*35 + l] * sws[l*35 + j];
    out[base + t] = acc;
}

// ---------------- host launch ----------------
extern "C" void kernel_launch(void* const* d_in, const int* in_sizes, int n_in,
                              void* d_out, int out_size) {
    const float* x      = (const float*)d_in[0];
    const float* cw1    = (const float*)d_in[1];
    const float* cb1    = (const float*)d_in[2];
    const float* cw2    = (const float*)d_in[3];
    const float* cb2    = (const float*)d_in[4];
    const float* gamma  = (const float*)d_in[5];
    const float* beta   = (const float*)d_in[6];
    const float* mw     = (const float*)d_in[7];
    const float* mb     = (const float*)d_in[8];
    const float* att    = (const float*)d_in[9];
    const float* A_ske  = (const float*)d_in[10];
    const float* ws     = (const float*)d_in[11];
    const float* bias   = (const float*)d_in[12];
    float* out = (float*)d_out;

    cudaFuncSetAttribute(k1_attm, cudaFuncAttributeMaxDynamicSharedMemorySize,
                         SM1_FLOATS * (int)sizeof(float));
    cudaFuncSetAttribute(k4_gcn, cudaFuncAttributeMaxDynamicSharedMemorySize,
                         SM4_FLOATS * (int)sizeof(float));

    k0_pre<<<NH, 256>>>(cw1, cb1, cw2, cb2);
    k1_attm<<<NB, 256, SM1_FLOATS * sizeof(float)>>>(x);
    k2_bn<<<NH*FEAT, 256>>>(gamma, beta);
    k3_soft<<<NB*NH, 256>>>(att, A_ske);
    k4_gcn<<<NB*NCHUNK, 256, SM4_FLOATS * sizeof(float)>>>(x, mw, mb);
    k5_out<<<(NB*CC*NN*LL)/280, 280>>>(ws, bias, out);
}

// round 4
// speedup vs baseline: 1.0020x; 1.0020x over previous
#include <cuda_runtime.h>

// Problem constants
#define NB    256      // batch
#define NH    3        // heads
#define CC    64       // channels (c == o)
#define NN    23       // nodes
#define LL    35       // seq len
#define FEAT  529      // 23*23
#define LC    5        // l-chunk size
#define NCHUNK 7       // 35 / 5
#define KINV  (1.0f/2240.0f)   // 1/(o*l)

// ---------------- device scratch (no allocations allowed) ----------------
__device__ float g_G[NH*64*65];        // G[h][c2][c1], rows padded to 65
__device__ float g_v1[NH*CC];          // v1[h][c] = sum_o cb2[h,o]*cw1[h,o,c]
__device__ float g_v2[NH*CC];          // v2[h][c] = sum_o cb1[h,o]*cw2[h,o,c]
__device__ float g_sc[NH];             // sum_o cb1*cb2
__device__ float g_attm[NB*NH*FEAT];   // pre-BN attention
__device__ float g_scale[NH*FEAT];     // gamma/sqrt(var+eps)
__device__ float g_shift[NH*FEAT];     // beta - mean*scale
__device__ float g_A[NB*NH*FEAT];      // final adjacency
__device__ float g_gcn[NB*CC*NN*LL];   // gcn output before seq matmul

// ---------------- k0: precompute G, v1, v2, s ----------------
__global__ void k0_pre(const float* __restrict__ cw1, const float* __restrict__ cb1,
                       const float* __restrict__ cw2, const float* __restrict__ cb2) {
    __shared__ float s1[64*64];
    __shared__ float s2[64*64];
    int h = blockIdx.x, t = threadIdx.x;
    for (int i = t; i < 4096; i += 256) { s1[i] = cw1[h*4096+i]; s2[i] = cw2[h*4096+i]; }
    __syncthreads();
    for (int e = t; e < 4096; e += 256) {
        int c2 = e >> 6, c1 = e & 63;
        float acc = 0.f;
        #pragma unroll 8
        for (int o = 0; o < 64; o++) acc += s2[o*64+c2] * s1[o*64+c1];
        g_G[h*64*65 + c2*65 + c1] = acc;
    }
    if (t < 64) {
        float a1 = 0.f, a2 = 0.f;
        for (int o = 0; o < 64; o++) {
            a1 += cb2[h*64+o] * s1[o*64+t];
            a2 += cb1[h*64+o] * s2[o*64+t];
        }
        g_v1[h*64+t] = a1;
        g_v2[h*64+t] = a2;
    }
    if (t == 64) {
        float a = 0.f;
        for (int o = 0; o < 64; o++) a += cb1[h*64+o]*cb2[h*64+o];
        g_sc[h] = a;
    }
}

// ---------------- k1: attention matrices (pre-BN) ----------------
// per-block (one batch b): Q[h,m,n] = sum_l X_l^T G_h X_l, plus bias terms.
// smem: sG[3*64*65] | sxt[64*115] | sW[192*23] | sXs[64*23] | st1[69] | st2[69]
#define SM1_FLOATS (NH*64*65 + 64*115 + 192*23 + 64*23 + 69 + 69)

__global__ __launch_bounds__(256, 2) void k1_attm(const float* __restrict__ x) {
    extern __shared__ float sm[];
    float* sG  = sm;                    // 12480
    float* sxt = sG  + NH*64*65;        // 7360  : [c][n*5+li]
    float* sW  = sxt + 64*115;          // 4416  : [(h*64+c2)*23+n]
    float* sXs = sW  + 192*23;          // 1472  : [c*23+n]
    float* st1 = sXs + 64*23;           // 69
    float* st2 = st1 + 69;              // 69

    int b = blockIdx.x, t = threadIdx.x;

    for (int i = t; i < NH*64*65; i += 256) sG[i] = g_G[i];
    for (int i = t; i < 1472; i += 256) sXs[i] = 0.f;

    // W-phase mapping: 64 row-tiles (3 rows) x 4 col-tiles (6 cols)
    int rt = t & 63, ct = t >> 6;
    int r0 = rt * 3;
    int n0 = ct * 6;

    // Q-phase mapping: 192 active threads; tile 3m x 3n per head
    int qh = t / 64, qs = t % 64;
    int qmt = qs & 7, qnt = qs >> 3;
    bool qact = (t < 192);
    int m0 = qmt * 3, nq0 = qnt * 3;

    float q[3][3];
    #pragma unroll
    for (int i = 0; i < 3; i++)
        #pragma unroll
        for (int j = 0; j < 3; j++) q[i][j] = 0.f;

    __syncthreads();

    for (int ch = 0; ch < NCHUNK; ch++) {
        int l0 = ch * LC;
        for (int idx = t; idx < 7360; idx += 256) {
            int c = idx / 115, r = idx % 115;
            int n = r / 5, li = r % 5;
            sxt[idx] = x[((b*64 + c)*23 + n)*35 + l0 + li];
        }
        __syncthreads();

        // Xs accumulation (each entry owned by one thread, read only at the end)
        for (int e = t; e < 1472; e += 256) {
            float a = sXs[e];
            #pragma unroll
            for (int li = 0; li < 5; li++) a += sxt[e*5 + li];
            sXs[e] = a;
        }

        for (int li = 0; li < LC; li++) {
            // ---- W phase: W[h,c2,n] = sum_c1 G[h,c2,c1] * x[c1,n,li]
            float wacc[3][6];
            #pragma unroll
            for (int i = 0; i < 3; i++)
                #pragma unroll
                for (int j = 0; j < 6; j++) wacc[i][j] = 0.f;
            #pragma unroll 4
            for (int c1 = 0; c1 < 64; c1++) {
                float xv[6];
                #pragma unroll
                for (int j = 0; j < 6; j++) {
                    int nj = n0 + j; if (nj > 22) nj = 22;
                    xv[j] = sxt[c1*115 + nj*5 + li];
                }
                float gv[3];
                #pragma unroll
                for (int i = 0; i < 3; i++) gv[i] = sG[(r0 + i)*65 + c1];
                #pragma unroll
                for (int i = 0; i < 3; i++)
                    #pragma unroll
                    for (int j = 0; j < 6; j++) wacc[i][j] += gv[i] * xv[j];
            }
            #pragma unroll
            for (int i = 0; i < 3; i++)
                #pragma unroll
                for (int j = 0; j < 6; j++)
                    if (n0 + j < 23) sW[(r0 + i)*23 + n0 + j] = wacc[i][j];
            __syncthreads();

            // ---- Q phase: Q[h,m,n] += sum_c2 x[c2,m,li] * W[h,c2,n]
            if (qact) {
                #pragma unroll 4
                for (int c2 = 0; c2 < 64; c2++) {
                    float xm[3], wn[3];
                    #pragma unroll
                    for (int i = 0; i < 3; i++) {
                        int mi = m0 + i; if (mi > 22) mi = 22;
                        xm[i] = sxt[c2*115 + mi*5 + li];
                    }
                    #pragma unroll
                    for (int j = 0; j < 3; j++) {
                        int nj = nq0 + j; if (nj > 22) nj = 22;
                        wn[j] = sW[(qh*64 + c2)*23 + nj];
                    }
                    #pragma unroll
                    for (int i = 0; i < 3; i++)
                        #pragma unroll
                        for (int j = 0; j < 3; j++) q[i][j] += xm[i] * wn[j];
                }
            }
            __syncthreads();
        }
    }

    // bias-correction vectors
    if (t < 69) {
        int h = t / 23, n = t % 23;
        float a = 0.f;
        #pragma unroll 8
        for (int c = 0; c < 64; c++) a += g_v1[h*64 + c] * sXs[c*23 + n];
        st1[t] = a;
    } else if (t < 138) {
        int tt = t - 69;
        int h = tt / 23, m = tt % 23;
        float a = 0.f;
        #pragma unroll 8
        for (int c = 0; c < 64; c++) a += g_v2[h*64 + c] * sXs[c*23 + m];
        st2[tt] = a;
    }
    __syncthreads();

    if (qact) {
        float base = 35.0f * g_sc[qh];
        #pragma unroll
        for (int i = 0; i < 3; i++) {
            int m = m0 + i; if (m >= 23) continue;
            #pragma unroll
            for (int j = 0; j < 3; j++) {
                int n = nq0 + j; if (n >= 23) continue;
                float val = (q[i][j] + st2[qh*23 + m] + st1[qh*23 + n] + base) * KINV;
                g_attm[(b*NH + qh)*FEAT + m*23 + n] = val;
            }
        }
    }
}

// ---------------- k2: BN batch stats -> fused scale/shift ----------------
__global__ void k2_bn(const float* __restrict__ gamma, const float* __restrict__ beta) {
    __shared__ float ss[256];
    __shared__ float sq[256];
    int f = blockIdx.x;          // 0 .. 1586 = h*529 + feat
    int t = threadIdx.x;
    float v = g_attm[t*(NH*FEAT) + f];
    ss[t] = v; sq[t] = v*v;
    __syncthreads();
    for (int s = 128; s > 0; s >>= 1) {
        if (t < s) { ss[t] += ss[t+s]; sq[t] += sq[t+s]; }
        __syncthreads();
    }
    if (t == 0) {
        float mean = ss[0] * (1.0f/256.0f);
        float var  = sq[0] * (1.0f/256.0f) - mean*mean;
        float sc = gamma[f] * rsqrtf(var + 1e-5f);
        g_scale[f] = sc;
        g_shift[f] = beta[f] - mean * sc;
    }
}

// ---------------- k3: BN apply + softmax(axis=-2) + A assembly ----------------
__global__ void k3_soft(const float* __restrict__ att, const float* __restrict__ A_ske) {
    __shared__ float sy[FEAT];
    int bh = blockIdx.x;         // b*3 + h
    int h = bh % 3;
    int t = threadIdx.x;
    for (int e = t; e < FEAT; e += 256)
        sy[e] = g_attm[bh*FEAT + e] * g_scale[h*FEAT + e] + g_shift[h*FEAT + e];
    __syncthreads();
    if (t < 23) {   // softmax over rows m, column t
        float mx = -1e30f;
        for (int m = 0; m < 23; m++) mx = fmaxf(mx, sy[m*23 + t]);
        float s = 0.f;
        for (int m = 0; m < 23; m++) {
            float e = expf(sy[m*23 + t] - mx);
            sy[m*23 + t] = e; s += e;
        }
        float inv = 1.0f / s;
        for (int m = 0; m < 23; m++) sy[m*23 + t] *= inv;
    }
    __syncthreads();
    for (int e = t; e < FEAT; e += 256)
        g_A[bh*FEAT + e] = A_ske[h*FEAT + e] + att[h*FEAT + e] + sy[e];
}

// ---------------- k4: graph convolution -> g_gcn ----------------
// block = (b, l-chunk). MX[h] = mw[h] @ X_chunk, gcn += A[h]^T-contract(MX)
// smem: sA[3*529] | sxt[64*115] | sMX[64*115] | smw[64*65]
#define SM4_FLOATS (NH*FEAT + 64*115 + 64*115 + 64*65)

__global__ __launch_bounds__(256, 2) void k4_gcn(const float* __restrict__ x,
                                                 const float* __restrict__ mw,
                                                 const float* __restrict__ mb) {
    extern __shared__ float sm[];
    float* sA  = sm;                  // 1587
    float* sxt = sA  + NH*FEAT;       // 7360 : [c][n*5+li]
    float* sMX = sxt + 64*115;        // 7360 : [o][n*5+li]
    float* smw = sMX + 64*115;        // 4160 : [o*65+c]

    int blk = blockIdx.x;
    int b = blk / NCHUNK, ch = blk % NCHUNK;
    int l0 = ch * LC;
    int t = threadIdx.x;

    for (int i = t; i < NH*FEAT; i += 256) sA[i] = g_A[b*NH*FEAT + i];
    for (int idx = t; idx < 7360; idx += 256) {
        int c = idx / 115, r = idx % 115;
        int n = r / 5, li = r % 5;
        sxt[idx] = x[((b*64 + c)*23 + n)*35 + l0 + li];
    }

    // MX mapping: 16 o-tiles (stride-16 interleave, 4 rows) x 15 col-tiles (8 cols)
    int ot = t & 15, qt = t >> 4;
    bool mact = (qt < 15);
    int col0 = qt * 8;

    // gcn accumulator mapping: o = t%64, m-tile = t/64 (6 m) x 5 li
    int go = t & 63, gmt = t >> 6;
    int gm0 = gmt * 6;
    float gacc[6][5];
    #pragma unroll
    for (int j = 0; j < 6; j++)
        #pragma unroll
        for (int li = 0; li < 5; li++) gacc[j][li] = 0.f;

    __syncthreads();

    for (int h = 0; h < NH; h++) {
        for (int i = t; i < 4096; i += 256) {
            int o = i >> 6, c = i & 63;
            smw[o*65 + c] = mw[(h*64 + o)*64 + c];
        }
        __syncthreads();

        // MX = mw[h] @ X  (outputs 64 x 115)
        if (mact) {
            float acc[4][8];
            #pragma unroll
            for (int i = 0; i < 4; i++)
                #pragma unroll
                for (int j = 0; j < 8; j++) acc[i][j] = 0.f;
            #pragma unroll 4
            for (int c = 0; c < 64; c++) {
                float wv[4], xv[8];
                #pragma unroll
                for (int i = 0; i < 4; i++) wv[i] = smw[(ot + i*16)*65 + c];
                #pragma unroll
                for (int j = 0; j < 8; j++) {
                    int col = col0 + j;
                    xv[j] = (col < 115) ? sxt[c*115 + col] : 0.f;
                }
                #pragma unroll
                for (int i = 0; i < 4; i++)
                    #pragma unroll
                    for (int j = 0; j < 8; j++) acc[i][j] += wv[i] * xv[j];
            }
            #pragma unroll
            for (int i = 0; i < 4; i++)
                #pragma unroll
                for (int j = 0; j < 8; j++) {
                    int col = col0 + j;
                    if (col < 115) sMX[(ot + i*16)*115 + col] = acc[i][j];
                }
        }
        __syncthreads();

        // gcn[o,m,li] += sum_n MX[o,n,li] * A[h,n,m]
        #pragma unroll 1
        for (int n = 0; n < 23; n++) {
            float mx[5], av[6];
            #pragma unroll
            for (int li = 0; li < 5; li++) mx[li] = sMX[go*115 + n*5 + li];
            #pragma unroll
            for (int j = 0; j < 6; j++) {
                int m = gm0 + j; if (m > 22) m = 22;
                av[j] = sA[h*FEAT + n*23 + m];
            }
            #pragma unroll
            for (int j = 0; j < 6; j++)
                #pragma unroll
                for (int li = 0; li < 5; li++) gacc[j][li] += av[j] * mx[li];
        }
        __syncthreads();
    }

    float mbs = mb[go] + mb[64 + go] + mb[128 + go];
    #pragma unroll
    for (int j = 0; j < 6; j++) {
        int m = gm0 + j; if (m >= 23) continue;
        #pragma unroll
        for (int li = 0; li < 5; li++)
            g_gcn[((b*64 + go)*23 + m)*35 + l0 + li] = gacc[j][li] + mbs;
    }
}

// ---------------- k5: out = gcn @ weight_seq + bias ----------------
__global__ void k5_out(const float* __restrict__ ws, const float* __restrict__ bias,
                       float* __restrict__ out) {
    __shared__ float sws[LL*LL];
    __shared__ float sb[LL];
    __shared__ float srow[280];
    int t = threadIdx.x;
    for (int i = t; i < LL*LL; i += 280) sws[i] = ws[i];
    if (t < LL) sb[t] = bias[t];
    int base = blockIdx.x * 280;
    srow[t] = g_gcn[base + t];
    __syncthreads();
    int r = t / 35, j = t % 35;
    float acc = sb[j];
    #pragma unroll
    for (int l = 0; l < 35; l++) acc += srow[r*35 + l] * sws[l*35 + j];
    out[base + t] = acc;
}

// ---------------- host launch ----------------
extern "C" void kernel_launch(void* const* d_in, const int* in_sizes, int n_in,
                              void* d_out, int out_size) {
    const float* x      = (const float*)d_in[0];
    const float* cw1    = (const float*)d_in[1];
    const float* cb1    = (const float*)d_in[2];
    const float* cw2    = (const float*)d_in[3];
    const float* cb2    = (const float*)d_in[4];
    const float* gamma  = (const float*)d_in[5];
    const float* beta   = (const float*)d_in[6];
    const float* mw     = (const float*)d_in[7];
    const float* mb     = (const float*)d_in[8];
    const float* att    = (const float*)d_in[9];
    const float* A_ske  = (const float*)d_in[10];
    const float* ws     = (const float*)d_in[11];
    const float* bias   = (const float*)d_in[12];
    float* out = (float*)d_out;

    cudaFuncSetAttribute(k1_attm, cudaFuncAttributeMaxDynamicSharedMemorySize,
                         SM1_FLOATS * (int)sizeof(float));
    cudaFuncSetAttribute(k4_gcn, cudaFuncAttributeMaxDynamicSharedMemorySize,
                         SM4_FLOATS * (int)sizeof(float));

    k0_pre<<<NH, 256>>>(cw1, cb1, cw2, cb2);
    k1_attm<<<NB, 256, SM1_FLOATS * sizeof(float)>>>(x);
    k2_bn<<<NH*FEAT, 256>>>(gamma, beta);
    k3_soft<<<NB*NH, 256>>>(att, A_ske);
    k4_gcn<<<NB*NCHUNK, 256, SM4_FLOATS * sizeof(float)>>>(x, mw, mb);
    k5_out<<<(NB*CC*NN*LL)/280, 280>>>(ws, bias, out);
}